// round 14
// baseline (speedup 1.0000x reference)
#include <cuda_runtime.h>
#include <cuda_fp16.h>
#include <math.h>
#include <stdint.h>

#define TT 2048
#define DIMD 2048
#define NH 16
#define NKVH 4
#define HD 128
#define NQ (NH*HD)     // 2048
#define NKV (NKVH*HD)  // 512
#define REP (NH/NKVH)  // 4
#define QKVW 3072

// Scratch (device globals; allocation in kernel_launch is forbidden)
__device__ __half g_qkvh[TT*QKVW];    // fp16 Q(roped)|K(roped)|V
__device__ __half g_atth[TT*NQ];      // fp16 attention output
__device__ __half g_xh  [TT*DIMD];
__device__ __half g_wqkvh[QKVW*DIMD]; // rows: wq | wk | wv
__device__ __half g_worh[DIMD*NQ];
__device__ unsigned g_ctrs[20];       // [1]=FA steal [2]=oproj steal [3..18]=done[qb]
#define CTR_FA 1
#define CTR_OP 2
#define DONE_B 3

// ---------------------------------------------------------------------------
// helpers
// ---------------------------------------------------------------------------
#define R_X   (TT*DIMD/4)
#define R_WQ  (NQ*DIMD/4)
#define R_WKV (NKV*DIMD/4)
#define R_TOT (R_X + R_WQ + 2*R_WKV + NQ*DIMD/4)

__global__ void round_all_kernel(const float* __restrict__ x,
                                 const float* __restrict__ wq,
                                 const float* __restrict__ wk,
                                 const float* __restrict__ wv,
                                 const float* __restrict__ wo,
                                 __half* __restrict__ xh,
                                 __half* __restrict__ wqkvh,
                                 __half* __restrict__ worh)
{
    int i = blockIdx.x * blockDim.x + threadIdx.x;
    if (i >= R_TOT) return;
    const float* in; __half* out; int j = i;
    if (j < R_X)                   { in = x;  out = xh; }
    else if ((j -= R_X)   < R_WQ)  { in = wq; out = wqkvh; }
    else if ((j -= R_WQ)  < R_WKV) { in = wk; out = wqkvh + (size_t)NQ*DIMD; }
    else if ((j -= R_WKV) < R_WKV) { in = wv; out = wqkvh + (size_t)(NQ+NKV)*DIMD; }
    else { j -= R_WKV;               in = wo; out = worh; }
    float4 v = ((const float4*)in)[j];
    __half2 h0 = __floats2half2_rn(v.x, v.y);
    __half2 h1 = __floats2half2_rn(v.z, v.w);
    ((__half2*)out)[2*j]   = h0;
    ((__half2*)out)[2*j+1] = h1;
}

__device__ __forceinline__ void cp_async16(unsigned saddr, const void* g) {
    asm volatile("cp.async.cg.shared.global [%0], [%1], 16;\n"
                 :: "r"(saddr), "l"(g));
}
__device__ __forceinline__ void cp_commit() {
    asm volatile("cp.async.commit_group;\n");
}
__device__ __forceinline__ void cp_wait0() {
    asm volatile("cp.async.wait_group 0;\n");
}
__device__ __forceinline__ void cp_wait1() {
    asm volatile("cp.async.wait_group 1;\n");
}

__device__ __forceinline__ void mma_f16(float c[4], const uint4& a,
                                        unsigned b0, unsigned b1) {
    asm volatile(
        "mma.sync.aligned.m16n8k16.row.col.f32.f16.f16.f32 "
        "{%0,%1,%2,%3}, {%4,%5,%6,%7}, {%8,%9}, {%0,%1,%2,%3};\n"
        : "+f"(c[0]), "+f"(c[1]), "+f"(c[2]), "+f"(c[3])
        : "r"(a.x), "r"(a.y), "r"(a.z), "r"(a.w), "r"(b0), "r"(b1));
}

__device__ __forceinline__ void ldsm_x4(uint4& d, unsigned addr) {
    asm volatile(
        "ldmatrix.sync.aligned.m8n8.x4.shared.b16 {%0,%1,%2,%3}, [%4];\n"
        : "=r"(d.x), "=r"(d.y), "=r"(d.z), "=r"(d.w) : "r"(addr));
}
__device__ __forceinline__ void ldsm_x4_t(uint4& d, unsigned addr) {
    asm volatile(
        "ldmatrix.sync.aligned.m8n8.x4.trans.shared.b16 {%0,%1,%2,%3}, [%4];\n"
        : "=r"(d.x), "=r"(d.y), "=r"(d.z), "=r"(d.w) : "r"(addr));
}

__device__ __forceinline__ unsigned pack_h2(float lo, float hi) {
    __half2 h = __floats2half2_rn(lo, hi);
    return *reinterpret_cast<unsigned*>(&h);
}

__device__ __forceinline__ unsigned ld_acq(const unsigned* p) {
    unsigned v;
    asm volatile("ld.acquire.gpu.u32 %0, [%1];" : "=r"(v) : "l"(p));
    return v;
}

// ---------------------------------------------------------------------------
// Shared GEMM mainloop: 128x128 tile, BK=64 halves, stride-72 smem,
// 3-stage cp.async ring, one barrier per k-iter.
// ---------------------------------------------------------------------------
#define GK 2048
#define SASTH 72
#define GASZH (128*SASTH)
#define GSTGH (2*GASZH)
#define GEMM_SMEM (3*GSTGH*2)    // 110592 B

__device__ __forceinline__ void gemm_mainloop(
    const __half* __restrict__ A, const __half* __restrict__ B,
    int bm, int bn, float c[2][8][4],
    int tid, int a_row, int a_colh, int b_row, int b_colh,
    unsigned smem_base)
{
#pragma unroll
    for (int mi = 0; mi < 2; mi++)
#pragma unroll
        for (int nj = 0; nj < 8; nj++)
#pragma unroll
            for (int r = 0; r < 4; r++) c[mi][nj][r] = 0.f;

    auto load_stage = [&](int s, int kt) {
        int k0 = kt * 64;
        unsigned sa = smem_base + (unsigned)(s * GSTGH) * 2u;
        unsigned sb = sa + (unsigned)GASZH * 2u;
#pragma unroll
        for (int i = 0; i < 4; i++) {
            int idx = tid + 256 * i;
            int row = idx >> 3;
            int c8  = (idx & 7) * 8;
            cp_async16(sa + (unsigned)(row * SASTH + c8) * 2u,
                       &A[(size_t)(bm + row) * GK + k0 + c8]);
            cp_async16(sb + (unsigned)(row * SASTH + c8) * 2u,
                       &B[(size_t)(bn + row) * GK + k0 + c8]);
        }
        cp_commit();
    };

    load_stage(0, 0);
    load_stage(1, 1);
    const int KT = GK / 64;

    int st = 0;
    for (int kt = 0; kt < KT; kt++) {
        if (kt + 1 < KT) cp_wait1(); else cp_wait0();
        __syncthreads();
        if (kt + 2 < KT) {
            int s2 = st + 2; if (s2 >= 3) s2 -= 3;
            load_stage(s2, kt + 2);
        }

        unsigned sA = smem_base + (unsigned)(st * GSTGH) * 2u;
        unsigned sB = sA + (unsigned)GASZH * 2u;

#pragma unroll
        for (int ks = 0; ks < 4; ks++) {
            int k0 = ks * 16;
            uint4 a[2], bp[4];
#pragma unroll
            for (int mi = 0; mi < 2; mi++)
                ldsm_x4(a[mi], sA + (unsigned)((a_row + mi*16) * SASTH
                                               + a_colh + k0) * 2u);
#pragma unroll
            for (int p = 0; p < 4; p++)
                ldsm_x4(bp[p], sB + (unsigned)((b_row + p*16) * SASTH
                                               + b_colh + k0) * 2u);
#pragma unroll
            for (int mi = 0; mi < 2; mi++)
#pragma unroll
                for (int p = 0; p < 4; p++) {
                    mma_f16(c[mi][2*p  ], a[mi], bp[p].x, bp[p].y);
                    mma_f16(c[mi][2*p+1], a[mi], bp[p].z, bp[p].w);
                }
        }
        if (++st == 3) st = 0;
    }
}

// ---------------------------------------------------------------------------
// QKV GEMM + fused RoPE/fp16 epilogue (R13, validated). Grid (24, 16), occ 2.
// ---------------------------------------------------------------------------
__global__ __launch_bounds__(256, 2) void qkv_gemm_kernel(
    const __half* __restrict__ A, const __half* __restrict__ B,
    __half* __restrict__ qkvh,
    const float* __restrict__ cs, const float* __restrict__ sn, float qscale)
{
    extern __shared__ float smf[];
    __half* smh = (__half*)smf;
    int bx = blockIdx.x;
    int bm = blockIdx.y * 128, bn = bx * 128;
    int tid = threadIdx.x;
    int lane = tid & 31, wid = tid >> 5;
    int wm = (wid & 3) * 32;
    int wn = (wid >> 2) * 64;
    int g = lane >> 2, t = lane & 3;

    int lrow = lane & 7;
    int am   = lane >> 3;
    int a_row  = wm + ((am & 1) << 3) + lrow;
    int a_colh = (am >> 1) << 3;
    int b_row  = wn + ((am >> 1) << 3) + lrow;
    int b_colh = (am & 1) << 3;

    unsigned smem_base = (unsigned)__cvta_generic_to_shared(smh);

    float c[2][8][4];
    gemm_mainloop(A, B, bm, bn, c, tid, a_row, a_colh, b_row, b_colh,
                  smem_base);

    if (bx >= 20) {
#pragma unroll
        for (int mi = 0; mi < 2; mi++) {
#pragma unroll
            for (int nj = 0; nj < 8; nj++) {
                int row0 = bm + wm + mi * 16 + g;
                int col  = bn + wn + nj * 8 + 2 * t;
                *(__half2*)&qkvh[(size_t)row0 * QKVW + col] =
                    __floats2half2_rn(c[mi][nj][0], c[mi][nj][1]);
                *(__half2*)&qkvh[(size_t)(row0 + 8) * QKVW + col] =
                    __floats2half2_rn(c[mi][nj][2], c[mi][nj][3]);
            }
        }
        return;
    }

    __syncthreads();
    float* stg = smf;  // [128][132]
#pragma unroll
    for (int mi = 0; mi < 2; mi++) {
#pragma unroll
        for (int nj = 0; nj < 8; nj++) {
            int row = wm + mi * 16 + g;
            int col = wn + nj * 8 + 2 * t;
            stg[row*132 + col]       = c[mi][nj][0];
            stg[row*132 + col + 1]   = c[mi][nj][1];
            stg[(row+8)*132 + col]   = c[mi][nj][2];
            stg[(row+8)*132 + col+1] = c[mi][nj][3];
        }
    }
    __syncthreads();

    float scale = (bx < 16) ? qscale : 1.0f;
#pragma unroll 4
    for (int rr = 0; rr < 16; rr++) {
        int row = wid * 16 + rr;
        int tok = bm + row;
        float2 cv = *(const float2*)&cs[(size_t)tok * HD + 2*lane];
        float2 sv = *(const float2*)&sn[(size_t)tok * HD + 2*lane];
        float2 ulo = *(const float2*)&stg[row*132 + 2*lane];
        float2 uhi = *(const float2*)&stg[row*132 + 64 + 2*lane];
        __half2 ha = __floats2half2_rn((ulo.x*cv.x - uhi.x*sv.x) * scale,
                                       (ulo.y*cv.y - uhi.y*sv.y) * scale);
        __half2 hb = __floats2half2_rn((uhi.x*cv.x + ulo.x*sv.x) * scale,
                                       (uhi.y*cv.y + ulo.y*sv.y) * scale);
        *(__half2*)&qkvh[(size_t)tok * QKVW + bn + 2*lane]      = ha;
        *(__half2*)&qkvh[(size_t)tok * QKVW + bn + 64 + 2*lane] = hb;
    }
}

// ---------------------------------------------------------------------------
// FUSED flash-attention + output-projection persistent kernel.
// Phase A: FA items (qb heavy-first). Completion -> release done[qb].
// Phase B: oproj tiles ordered m=15..0, acquire-wait on done[m]==16.
// Grid = #SMs, 256 threads, dyn smem 110592 (FA uses 104448 of it).
// ---------------------------------------------------------------------------
#define FAQ 128
#define FA_ST 136
#define FA_QSZH (FAQ*FA_ST)
#define FA_KSZH (64*FA_ST)
#define FA_KVSZH (2*FA_KSZH)
#define FA_ITEMS (NH * (TT/FAQ))             // 256
#define OP_ITEMS (16*16)                     // 256

__global__ __launch_bounds__(256, 1) void fa_oproj_kernel(
    __half* __restrict__ att, const __half* __restrict__ worh,
    float* __restrict__ out)
{
    extern __shared__ float smf[];
    __half* smh = (__half*)smf;
    __shared__ unsigned s_item;
    int tid = threadIdx.x;
    int lane = tid & 31, wid = tid >> 5;
    int g = lane >> 2, t = lane & 3;
    int w16 = wid * 16;

    int lrow = lane & 7;
    int am   = lane >> 3;
    int qa_row  = w16 + ((am & 1) << 3) + lrow;
    int qa_colh = (am >> 1) << 3;
    int kb_row  = ((am >> 1) << 3) + lrow;
    int kb_colh = (am & 1) << 3;
    int vb_row  = ((am & 1) << 3) + lrow;
    int vb_colh = (am >> 1) << 3;

    unsigned smem_base = (unsigned)__cvta_generic_to_shared(smh);

    // ================= Phase A: flash attention =================
    while (true) {
        if (tid == 0) s_item = atomicAdd(&g_ctrs[CTR_FA], 1u);
        __syncthreads();
        unsigned r = s_item;
        if (r >= FA_ITEMS) break;
        int qb = (TT/FAQ) - 1 - (int)(r >> 4);
        int h  = (int)(r & 15u);
        int g0 = h / REP;

#pragma unroll
        for (int i = 0; i < 8; i++) {
            int idx = tid + 256 * i;
            int rr = idx >> 4;
            int c8 = (idx & 15) * 8;
            *(uint4*)&smh[rr*FA_ST + c8] =
                *(const uint4*)&g_qkvh[(size_t)(qb*FAQ + rr) * QKVW + h*HD + c8];
        }

        auto load_kv = [&](int kb, int s) {
            const __half* Kg = &g_qkvh[(size_t)(kb*64) * QKVW + NQ + g0*HD];
            const __half* Vg = Kg + NKV;
            unsigned kbase = smem_base + (unsigned)(FA_QSZH + s*FA_KVSZH) * 2u;
            unsigned vbase = kbase + (unsigned)FA_KSZH * 2u;
#pragma unroll
            for (int i = 0; i < 4; i++) {
                int idx = tid + 256 * i;
                int rr = idx >> 4;
                int c8 = (idx & 15) * 8;
                cp_async16(kbase + (unsigned)(rr*FA_ST + c8) * 2u,
                           Kg + (size_t)rr*QKVW + c8);
                cp_async16(vbase + (unsigned)(rr*FA_ST + c8) * 2u,
                           Vg + (size_t)rr*QKVW + c8);
            }
            cp_commit();
        };

        float o[16][4];
#pragma unroll
        for (int nj = 0; nj < 16; nj++)
#pragma unroll
            for (int rr = 0; rr < 4; rr++) o[nj][rr] = 0.f;
        float m0 = -1e30f, m1 = -1e30f, l0 = 0.f, l1 = 0.f;
        uint4 qa[8];

        const int kb_max = 2*qb + 1;
        load_kv(0, 0);

        for (int kb = 0; kb <= kb_max; kb++) {
            if (kb < kb_max) { load_kv(kb + 1, (kb + 1) & 1); cp_wait1(); }
            else             { cp_wait0(); }
            __syncthreads();

            if (kb == 0) {
#pragma unroll
                for (int ks = 0; ks < 8; ks++)
                    ldsm_x4(qa[ks], smem_base + (unsigned)(qa_row*FA_ST
                                                   + qa_colh + ks*16)*2u);
            }

            unsigned sK = smem_base + (unsigned)(FA_QSZH + (kb & 1)*FA_KVSZH) * 2u;
            unsigned sV = sK + (unsigned)FA_KSZH * 2u;

            float s[8][4];
#pragma unroll
            for (int nj = 0; nj < 8; nj++)
#pragma unroll
                for (int rr = 0; rr < 4; rr++) s[nj][rr] = 0.f;

#pragma unroll
            for (int ks = 0; ks < 8; ks++) {
                int k0 = ks * 16;
                uint4 bp[4];
#pragma unroll
                for (int p = 0; p < 4; p++)
                    ldsm_x4(bp[p], sK + (unsigned)((kb_row + p*16)*FA_ST
                                                   + kb_colh + k0)*2u);
#pragma unroll
                for (int p = 0; p < 4; p++) {
                    mma_f16(s[2*p  ], qa[ks], bp[p].x, bp[p].y);
                    mma_f16(s[2*p+1], qa[ks], bp[p].z, bp[p].w);
                }
            }

            if (kb >= 2*qb) {
                int r0 = qb*FAQ + w16 + g, r1 = r0 + 8;
                int cb0 = kb*64 + 2*t;
#pragma unroll
                for (int nj = 0; nj < 8; nj++) {
                    int c0 = cb0 + nj*8, c1 = c0 + 1;
                    if (c0 > r0) s[nj][0] = -1e30f;
                    if (c1 > r0) s[nj][1] = -1e30f;
                    if (c0 > r1) s[nj][2] = -1e30f;
                    if (c1 > r1) s[nj][3] = -1e30f;
                }
            }

            float mx0 = -1e30f, mx1 = -1e30f;
#pragma unroll
            for (int nj = 0; nj < 8; nj++) {
                mx0 = fmaxf(mx0, fmaxf(s[nj][0], s[nj][1]));
                mx1 = fmaxf(mx1, fmaxf(s[nj][2], s[nj][3]));
            }
            mx0 = fmaxf(mx0, __shfl_xor_sync(0xffffffffu, mx0, 1));
            mx0 = fmaxf(mx0, __shfl_xor_sync(0xffffffffu, mx0, 2));
            mx1 = fmaxf(mx1, __shfl_xor_sync(0xffffffffu, mx1, 1));
            mx1 = fmaxf(mx1, __shfl_xor_sync(0xffffffffu, mx1, 2));
            float mn0 = fmaxf(m0, mx0), mn1 = fmaxf(m1, mx1);
            float al0 = __expf(m0 - mn0), al1 = __expf(m1 - mn1);
            m0 = mn0; m1 = mn1;

            float rs0 = 0.f, rs1 = 0.f;
#pragma unroll
            for (int nj = 0; nj < 8; nj++) {
                s[nj][0] = __expf(s[nj][0] - mn0);
                s[nj][1] = __expf(s[nj][1] - mn0);
                s[nj][2] = __expf(s[nj][2] - mn1);
                s[nj][3] = __expf(s[nj][3] - mn1);
                rs0 += s[nj][0] + s[nj][1];
                rs1 += s[nj][2] + s[nj][3];
            }
            rs0 += __shfl_xor_sync(0xffffffffu, rs0, 1);
            rs0 += __shfl_xor_sync(0xffffffffu, rs0, 2);
            rs1 += __shfl_xor_sync(0xffffffffu, rs1, 1);
            rs1 += __shfl_xor_sync(0xffffffffu, rs1, 2);
            l0 = l0 * al0 + rs0;
            l1 = l1 * al1 + rs1;

#pragma unroll
            for (int nj = 0; nj < 16; nj++) {
                o[nj][0] *= al0; o[nj][1] *= al0;
                o[nj][2] *= al1; o[nj][3] *= al1;
            }

#pragma unroll
            for (int kt = 0; kt < 4; kt++) {
                uint4 a;
                a.x = pack_h2(s[2*kt  ][0], s[2*kt  ][1]);
                a.y = pack_h2(s[2*kt  ][2], s[2*kt  ][3]);
                a.z = pack_h2(s[2*kt+1][0], s[2*kt+1][1]);
                a.w = pack_h2(s[2*kt+1][2], s[2*kt+1][3]);
#pragma unroll
                for (int q = 0; q < 8; q++) {
                    uint4 bp;
                    ldsm_x4_t(bp, sV + (unsigned)((16*kt + vb_row)*FA_ST
                                                  + q*16 + vb_colh)*2u);
                    mma_f16(o[2*q  ], a, bp.x, bp.y);
                    mma_f16(o[2*q+1], a, bp.z, bp.w);
                }
            }
            __syncthreads();
        }

        float il0 = 1.0f / l0, il1 = 1.0f / l1;
#pragma unroll
        for (int nj = 0; nj < 16; nj++) {
            int row0 = qb*FAQ + w16 + g;
            int col  = h*HD + nj*8 + 2*t;
            __half2 v0 = __floats2half2_rn(o[nj][0]*il0, o[nj][1]*il0);
            __half2 v1 = __floats2half2_rn(o[nj][2]*il1, o[nj][3]*il1);
            *(__half2*)&att[(size_t)row0 * NQ + col]       = v0;
            *(__half2*)&att[(size_t)(row0 + 8) * NQ + col] = v1;
        }
        // release: make this item's att rows visible, then count it
        __threadfence();
        __syncthreads();
        if (tid == 0) atomicAdd(&g_ctrs[DONE_B + qb], 1u);
    }

    // ================= Phase B: output projection =================
    {
        int wm = (wid & 3) * 32;
        int wn = (wid >> 2) * 64;
        int a_row  = wm + ((am & 1) << 3) + lrow;
        int a_colh = (am >> 1) << 3;
        int b_row  = wn + ((am >> 1) << 3) + lrow;
        int b_colh = (am & 1) << 3;

        while (true) {
            if (tid == 0) s_item = atomicAdd(&g_ctrs[CTR_OP], 1u);
            __syncthreads();
            unsigned it = s_item;
            if (it >= OP_ITEMS) break;
            int m = 15 - (int)(it >> 4);     // matches FA completion order
            int n = (int)(it & 15u);
            int bm = m * 128, bn = n * 128;

            if (tid == 0) {
                while (ld_acq(&g_ctrs[DONE_B + m]) < 16u) { }
            }
            __syncthreads();

            float c[2][8][4];
            gemm_mainloop(att, worh, bm, bn, c, tid,
                          a_row, a_colh, b_row, b_colh, smem_base);

#pragma unroll
            for (int mi = 0; mi < 2; mi++) {
#pragma unroll
                for (int nj = 0; nj < 8; nj++) {
                    int row0 = bm + wm + mi * 16 + g;
                    int col  = bn + wn + nj * 8 + 2 * t;
                    *(float2*)&out[(size_t)row0 * DIMD + col] =
                        make_float2(c[mi][nj][0], c[mi][nj][1]);
                    *(float2*)&out[(size_t)(row0 + 8) * DIMD + col] =
                        make_float2(c[mi][nj][2], c[mi][nj][3]);
                }
            }
            __syncthreads();
        }
    }
}

// ---------------------------------------------------------------------------
extern "C" void kernel_launch(void* const* d_in, const int* in_sizes, int n_in,
                              void* d_out, int out_size)
{
    const float* x  = (const float*)d_in[0];
    const float* wq = (const float*)d_in[1];
    const float* wk = (const float*)d_in[2];
    const float* wv = (const float*)d_in[3];
    const float* wo = (const float*)d_in[4];
    const float* cs = (const float*)d_in[5];
    const float* sn = (const float*)d_in[6];
    float* out = (float*)d_out;

    __half *qkvh, *atth, *xh, *wqkvh, *worh; void* ctrs;
    cudaGetSymbolAddress((void**)&qkvh,  g_qkvh);
    cudaGetSymbolAddress((void**)&atth,  g_atth);
    cudaGetSymbolAddress((void**)&xh,    g_xh);
    cudaGetSymbolAddress((void**)&wqkvh, g_wqkvh);
    cudaGetSymbolAddress((void**)&worh,  g_worh);
    cudaGetSymbolAddress(&ctrs,          g_ctrs);

    static int nsm = 0;
    if (nsm == 0) {
        cudaDeviceGetAttribute(&nsm, cudaDevAttrMultiProcessorCount, 0);
        if (nsm <= 0) nsm = 148;
        cudaFuncSetAttribute(qkv_gemm_kernel,
            cudaFuncAttributeMaxDynamicSharedMemorySize, GEMM_SMEM);
        cudaFuncSetAttribute(fa_oproj_kernel,
            cudaFuncAttributeMaxDynamicSharedMemorySize, GEMM_SMEM);
    }

    cudaMemsetAsync(ctrs, 0, 20*sizeof(unsigned));

    // Round inputs once to fp16 (10-bit mantissa — same as tf32)
    round_all_kernel<<<(R_TOT + 255)/256, 256>>>(
        x, wq, wk, wv, wo, xh, wqkvh, worh);

    // QKV projection with fused RoPE + fp16 epilogue
    const float scale = 0.08838834764831845f;  // 128^-0.5
    qkv_gemm_kernel<<<dim3(QKVW/128, TT/128), 256, GEMM_SMEM>>>(
        xh, wqkvh, qkvh, cs, sn, scale);

    // Fused flash attention + output projection (overlapped via readiness)
    fa_oproj_kernel<<<dim3(nsm, 1), 256, GEMM_SMEM>>>(atth, worh, out);
}

// round 15
// speedup vs baseline: 1.0679x; 1.0679x over previous
#include <cuda_runtime.h>
#include <cuda_fp16.h>
#include <math.h>
#include <stdint.h>

#define TT 2048
#define DIMD 2048
#define NH 16
#define NKVH 4
#define HD 128
#define NQ (NH*HD)     // 2048
#define NKV (NKVH*HD)  // 512
#define REP (NH/NKVH)  // 4
#define QKVW 3072

// Scratch (device globals; allocation in kernel_launch is forbidden)
__device__ __half g_qkvh[TT*QKVW];    // fp16 Q(roped)|K(roped)|V
__device__ __half g_atth[TT*NQ];      // fp16 attention output
__device__ __half g_xh  [TT*DIMD];
__device__ __half g_wqkvh[QKVW*DIMD]; // rows: wq | wk | wv
__device__ __half g_worh[DIMD*NQ];
__device__ unsigned g_ctrs[2];        // [1]=FA steal

// ---------------------------------------------------------------------------
// helpers
// ---------------------------------------------------------------------------
#define R_X   (TT*DIMD/4)
#define R_WQ  (NQ*DIMD/4)
#define R_WKV (NKV*DIMD/4)
#define R_TOT (R_X + R_WQ + 2*R_WKV + NQ*DIMD/4)

__global__ void round_all_kernel(const float* __restrict__ x,
                                 const float* __restrict__ wq,
                                 const float* __restrict__ wk,
                                 const float* __restrict__ wv,
                                 const float* __restrict__ wo,
                                 __half* __restrict__ xh,
                                 __half* __restrict__ wqkvh,
                                 __half* __restrict__ worh)
{
    int i = blockIdx.x * blockDim.x + threadIdx.x;
    if (i >= R_TOT) return;
    const float* in; __half* out; int j = i;
    if (j < R_X)                   { in = x;  out = xh; }
    else if ((j -= R_X)   < R_WQ)  { in = wq; out = wqkvh; }
    else if ((j -= R_WQ)  < R_WKV) { in = wk; out = wqkvh + (size_t)NQ*DIMD; }
    else if ((j -= R_WKV) < R_WKV) { in = wv; out = wqkvh + (size_t)(NQ+NKV)*DIMD; }
    else { j -= R_WKV;               in = wo; out = worh; }
    float4 v = ((const float4*)in)[j];
    __half2 h0 = __floats2half2_rn(v.x, v.y);
    __half2 h1 = __floats2half2_rn(v.z, v.w);
    ((__half2*)out)[2*j]   = h0;
    ((__half2*)out)[2*j+1] = h1;
}

__device__ __forceinline__ void cp_async16(unsigned saddr, const void* g) {
    asm volatile("cp.async.cg.shared.global [%0], [%1], 16;\n"
                 :: "r"(saddr), "l"(g));
}
__device__ __forceinline__ void cp_commit() {
    asm volatile("cp.async.commit_group;\n");
}
__device__ __forceinline__ void cp_wait0() {
    asm volatile("cp.async.wait_group 0;\n");
}
__device__ __forceinline__ void cp_wait1() {
    asm volatile("cp.async.wait_group 1;\n");
}

__device__ __forceinline__ void mma_f16(float c[4], const uint4& a,
                                        unsigned b0, unsigned b1) {
    asm volatile(
        "mma.sync.aligned.m16n8k16.row.col.f32.f16.f16.f32 "
        "{%0,%1,%2,%3}, {%4,%5,%6,%7}, {%8,%9}, {%0,%1,%2,%3};\n"
        : "+f"(c[0]), "+f"(c[1]), "+f"(c[2]), "+f"(c[3])
        : "r"(a.x), "r"(a.y), "r"(a.z), "r"(a.w), "r"(b0), "r"(b1));
}

__device__ __forceinline__ void ldsm_x4(uint4& d, unsigned addr) {
    asm volatile(
        "ldmatrix.sync.aligned.m8n8.x4.shared.b16 {%0,%1,%2,%3}, [%4];\n"
        : "=r"(d.x), "=r"(d.y), "=r"(d.z), "=r"(d.w) : "r"(addr));
}
__device__ __forceinline__ void ldsm_x4_t(uint4& d, unsigned addr) {
    asm volatile(
        "ldmatrix.sync.aligned.m8n8.x4.trans.shared.b16 {%0,%1,%2,%3}, [%4];\n"
        : "=r"(d.x), "=r"(d.y), "=r"(d.z), "=r"(d.w) : "r"(addr));
}

__device__ __forceinline__ unsigned pack_h2(float lo, float hi) {
    __half2 h = __floats2half2_rn(lo, hi);
    return *reinterpret_cast<unsigned*>(&h);
}

// ---------------------------------------------------------------------------
// Shared GEMM mainloop: 128x128 tile, BK=64 halves, stride-72 smem,
// 3-stage cp.async ring, one barrier per k-iter.
// ---------------------------------------------------------------------------
#define GK 2048
#define SASTH 72
#define GASZH (128*SASTH)
#define GSTGH (2*GASZH)
#define GEMM_SMEM (3*GSTGH*2)    // 110592 B

__device__ __forceinline__ void gemm_mainloop(
    const __half* __restrict__ A, const __half* __restrict__ B,
    int bm, int bn, float c[2][8][4],
    int tid, int a_row, int a_colh, int b_row, int b_colh,
    unsigned smem_base)
{
#pragma unroll
    for (int mi = 0; mi < 2; mi++)
#pragma unroll
        for (int nj = 0; nj < 8; nj++)
#pragma unroll
            for (int r = 0; r < 4; r++) c[mi][nj][r] = 0.f;

    auto load_stage = [&](int s, int kt) {
        int k0 = kt * 64;
        unsigned sa = smem_base + (unsigned)(s * GSTGH) * 2u;
        unsigned sb = sa + (unsigned)GASZH * 2u;
#pragma unroll
        for (int i = 0; i < 4; i++) {
            int idx = tid + 256 * i;
            int row = idx >> 3;
            int c8  = (idx & 7) * 8;
            cp_async16(sa + (unsigned)(row * SASTH + c8) * 2u,
                       &A[(size_t)(bm + row) * GK + k0 + c8]);
            cp_async16(sb + (unsigned)(row * SASTH + c8) * 2u,
                       &B[(size_t)(bn + row) * GK + k0 + c8]);
        }
        cp_commit();
    };

    load_stage(0, 0);
    load_stage(1, 1);
    const int KT = GK / 64;

    int st = 0;
    for (int kt = 0; kt < KT; kt++) {
        if (kt + 1 < KT) cp_wait1(); else cp_wait0();
        __syncthreads();
        if (kt + 2 < KT) {
            int s2 = st + 2; if (s2 >= 3) s2 -= 3;
            load_stage(s2, kt + 2);
        }

        unsigned sA = smem_base + (unsigned)(st * GSTGH) * 2u;
        unsigned sB = sA + (unsigned)GASZH * 2u;

#pragma unroll
        for (int ks = 0; ks < 4; ks++) {
            int k0 = ks * 16;
            uint4 a[2], bp[4];
#pragma unroll
            for (int mi = 0; mi < 2; mi++)
                ldsm_x4(a[mi], sA + (unsigned)((a_row + mi*16) * SASTH
                                               + a_colh + k0) * 2u);
#pragma unroll
            for (int p = 0; p < 4; p++)
                ldsm_x4(bp[p], sB + (unsigned)((b_row + p*16) * SASTH
                                               + b_colh + k0) * 2u);
#pragma unroll
            for (int mi = 0; mi < 2; mi++)
#pragma unroll
                for (int p = 0; p < 4; p++) {
                    mma_f16(c[mi][2*p  ], a[mi], bp[p].x, bp[p].y);
                    mma_f16(c[mi][2*p+1], a[mi], bp[p].z, bp[p].w);
                }
        }
        if (++st == 3) st = 0;
    }
}

// ---------------------------------------------------------------------------
// QKV GEMM + fused RoPE/fp16 epilogue. Grid (24, 16), occ 2.
// ---------------------------------------------------------------------------
__global__ __launch_bounds__(256, 2) void qkv_gemm_kernel(
    const __half* __restrict__ A, const __half* __restrict__ B,
    __half* __restrict__ qkvh,
    const float* __restrict__ cs, const float* __restrict__ sn, float qscale)
{
    extern __shared__ float smf[];
    __half* smh = (__half*)smf;
    int bx = blockIdx.x;
    int bm = blockIdx.y * 128, bn = bx * 128;
    int tid = threadIdx.x;
    int lane = tid & 31, wid = tid >> 5;
    int wm = (wid & 3) * 32;
    int wn = (wid >> 2) * 64;
    int g = lane >> 2, t = lane & 3;

    int lrow = lane & 7;
    int am   = lane >> 3;
    int a_row  = wm + ((am & 1) << 3) + lrow;
    int a_colh = (am >> 1) << 3;
    int b_row  = wn + ((am >> 1) << 3) + lrow;
    int b_colh = (am & 1) << 3;

    unsigned smem_base = (unsigned)__cvta_generic_to_shared(smh);

    float c[2][8][4];
    gemm_mainloop(A, B, bm, bn, c, tid, a_row, a_colh, b_row, b_colh,
                  smem_base);

    if (bx >= 20) {
#pragma unroll
        for (int mi = 0; mi < 2; mi++) {
#pragma unroll
            for (int nj = 0; nj < 8; nj++) {
                int row0 = bm + wm + mi * 16 + g;
                int col  = bn + wn + nj * 8 + 2 * t;
                *(__half2*)&qkvh[(size_t)row0 * QKVW + col] =
                    __floats2half2_rn(c[mi][nj][0], c[mi][nj][1]);
                *(__half2*)&qkvh[(size_t)(row0 + 8) * QKVW + col] =
                    __floats2half2_rn(c[mi][nj][2], c[mi][nj][3]);
            }
        }
        return;
    }

    __syncthreads();
    float* stg = smf;  // [128][132]
#pragma unroll
    for (int mi = 0; mi < 2; mi++) {
#pragma unroll
        for (int nj = 0; nj < 8; nj++) {
            int row = wm + mi * 16 + g;
            int col = wn + nj * 8 + 2 * t;
            stg[row*132 + col]       = c[mi][nj][0];
            stg[row*132 + col + 1]   = c[mi][nj][1];
            stg[(row+8)*132 + col]   = c[mi][nj][2];
            stg[(row+8)*132 + col+1] = c[mi][nj][3];
        }
    }
    __syncthreads();

    float scale = (bx < 16) ? qscale : 1.0f;
#pragma unroll 4
    for (int rr = 0; rr < 16; rr++) {
        int row = wid * 16 + rr;
        int tok = bm + row;
        float2 cv = *(const float2*)&cs[(size_t)tok * HD + 2*lane];
        float2 sv = *(const float2*)&sn[(size_t)tok * HD + 2*lane];
        float2 ulo = *(const float2*)&stg[row*132 + 2*lane];
        float2 uhi = *(const float2*)&stg[row*132 + 64 + 2*lane];
        __half2 ha = __floats2half2_rn((ulo.x*cv.x - uhi.x*sv.x) * scale,
                                       (ulo.y*cv.y - uhi.y*sv.y) * scale);
        __half2 hb = __floats2half2_rn((uhi.x*cv.x + ulo.x*sv.x) * scale,
                                       (uhi.y*cv.y + ulo.y*sv.y) * scale);
        *(__half2*)&qkvh[(size_t)tok * QKVW + bn + 2*lane]      = ha;
        *(__half2*)&qkvh[(size_t)tok * QKVW + bn + 64 + 2*lane] = hb;
    }
}

// ---------------------------------------------------------------------------
// Output projection GEMM: fp32 out. 128x128 tiles, occ 2, grid (16,16).
// ---------------------------------------------------------------------------
__global__ __launch_bounds__(256, 2) void oproj_gemm_kernel(
    const __half* __restrict__ A, const __half* __restrict__ B,
    float* __restrict__ C)
{
    extern __shared__ float smf[];
    __half* smh = (__half*)smf;
    int bm = blockIdx.y * 128, bn = blockIdx.x * 128;
    int tid = threadIdx.x;
    int lane = tid & 31, wid = tid >> 5;
    int wm = (wid & 3) * 32;
    int wn = (wid >> 2) * 64;
    int g = lane >> 2, t = lane & 3;

    int lrow = lane & 7;
    int am   = lane >> 3;
    int a_row  = wm + ((am & 1) << 3) + lrow;
    int a_colh = (am >> 1) << 3;
    int b_row  = wn + ((am >> 1) << 3) + lrow;
    int b_colh = (am & 1) << 3;

    unsigned smem_base = (unsigned)__cvta_generic_to_shared(smh);

    float c[2][8][4];
    gemm_mainloop(A, B, bm, bn, c, tid, a_row, a_colh, b_row, b_colh,
                  smem_base);

#pragma unroll
    for (int mi = 0; mi < 2; mi++) {
#pragma unroll
        for (int nj = 0; nj < 8; nj++) {
            int row0 = bm + wm + mi * 16 + g;
            int col  = bn + wn + nj * 8 + 2 * t;
            *(float2*)&C[(size_t)row0 * DIMD + col] =
                make_float2(c[mi][nj][0], c[mi][nj][1]);
            *(float2*)&C[(size_t)(row0 + 8) * DIMD + col] =
                make_float2(c[mi][nj][2], c[mi][nj][3]);
        }
    }
}

// ---------------------------------------------------------------------------
// fp16 flash attention, BQ=128, BKV=128 (halved softmax/barrier instances).
// 256 threads; Q frags cached in regs; S C-frag -> PV A-frag direct pack;
// V via ldmatrix.trans. Persistent work-steal over all SMs.
// smem: Q 128x136 + 2 stages x (K 128x136 + V 128x136) = 174080 B.
// ---------------------------------------------------------------------------
#define FAQ 128
#define FA_ST 136
#define FA_QSZH (FAQ*FA_ST)          // 17408 halves
#define FA_KSZH (128*FA_ST)          // 17408 halves (K tile)
#define FA_KVSZH (2*FA_KSZH)         // K + V per stage
#define FA_SMEM ((FA_QSZH + 2*FA_KVSZH)*2)   // 174080 B
#define FA_ITEMS (NH * (TT/FAQ))             // 256

__global__ __launch_bounds__(256, 1) void fa_f16_kernel(__half* __restrict__ att)
{
    extern __shared__ float smf[];
    __half* smh = (__half*)smf;
    __shared__ unsigned s_item;
    int tid = threadIdx.x;
    int lane = tid & 31, wid = tid >> 5;
    int g = lane >> 2, t = lane & 3;
    int w16 = wid * 16;

    int lrow = lane & 7;
    int am   = lane >> 3;
    int qa_row  = w16 + ((am & 1) << 3) + lrow;
    int qa_colh = (am >> 1) << 3;
    int kb_row  = ((am >> 1) << 3) + lrow;
    int kb_colh = (am & 1) << 3;
    int vb_row  = ((am & 1) << 3) + lrow;
    int vb_colh = (am >> 1) << 3;

    unsigned smem_base = (unsigned)__cvta_generic_to_shared(smh);

    while (true) {
        if (tid == 0) s_item = atomicAdd(&g_ctrs[1], 1u);
        __syncthreads();
        unsigned r = s_item;
        if (r >= FA_ITEMS) break;
        int qb = (TT/FAQ) - 1 - (int)(r >> 4);
        int h  = (int)(r & 15u);
        int g0 = h / REP;

        // Load Q tile
#pragma unroll
        for (int i = 0; i < 8; i++) {
            int idx = tid + 256 * i;
            int rr = idx >> 4;
            int c8 = (idx & 15) * 8;
            *(uint4*)&smh[rr*FA_ST + c8] =
                *(const uint4*)&g_qkvh[(size_t)(qb*FAQ + rr) * QKVW + h*HD + c8];
        }

        auto load_kv = [&](int kb, int s) {
            const __half* Kg = &g_qkvh[(size_t)(kb*128) * QKVW + NQ + g0*HD];
            const __half* Vg = Kg + NKV;
            unsigned kbase = smem_base + (unsigned)(FA_QSZH + s*FA_KVSZH) * 2u;
            unsigned vbase = kbase + (unsigned)FA_KSZH * 2u;
#pragma unroll
            for (int i = 0; i < 8; i++) {
                int idx = tid + 256 * i;   // 0..2047
                int rr = idx >> 4;         // 0..127
                int c8 = (idx & 15) * 8;
                cp_async16(kbase + (unsigned)(rr*FA_ST + c8) * 2u,
                           Kg + (size_t)rr*QKVW + c8);
                cp_async16(vbase + (unsigned)(rr*FA_ST + c8) * 2u,
                           Vg + (size_t)rr*QKVW + c8);
            }
            cp_commit();
        };

        float o[16][4];
#pragma unroll
        for (int nj = 0; nj < 16; nj++)
#pragma unroll
            for (int rr = 0; rr < 4; rr++) o[nj][rr] = 0.f;
        float m0 = -1e30f, m1 = -1e30f, l0 = 0.f, l1 = 0.f;
        uint4 qa[8];

        const int kb_max = qb;
        load_kv(0, 0);

        for (int kb = 0; kb <= kb_max; kb++) {
            if (kb < kb_max) { load_kv(kb + 1, (kb + 1) & 1); cp_wait1(); }
            else             { cp_wait0(); }
            __syncthreads();

            if (kb == 0) {
#pragma unroll
                for (int ks = 0; ks < 8; ks++)
                    ldsm_x4(qa[ks], smem_base + (unsigned)(qa_row*FA_ST
                                                   + qa_colh + ks*16)*2u);
            }

            unsigned sK = smem_base + (unsigned)(FA_QSZH + (kb & 1)*FA_KVSZH) * 2u;
            unsigned sV = sK + (unsigned)FA_KSZH * 2u;

            // ---- S = Q K^T : 16x128 per warp, s[16][4] ----
            float s[16][4];
#pragma unroll
            for (int nj = 0; nj < 16; nj++)
#pragma unroll
                for (int rr = 0; rr < 4; rr++) s[nj][rr] = 0.f;

#pragma unroll
            for (int ks = 0; ks < 8; ks++) {
                int k0 = ks * 16;
                uint4 bp[8];
#pragma unroll
                for (int p = 0; p < 8; p++)
                    ldsm_x4(bp[p], sK + (unsigned)((kb_row + p*16)*FA_ST
                                                   + kb_colh + k0)*2u);
#pragma unroll
                for (int p = 0; p < 8; p++) {
                    mma_f16(s[2*p  ], qa[ks], bp[p].x, bp[p].y);
                    mma_f16(s[2*p+1], qa[ks], bp[p].z, bp[p].w);
                }
            }

            // ---- causal mask (diagonal block only) ----
            if (kb == qb) {
                int r0 = w16 + g, r1 = r0 + 8;   // local row within 128
                int c0b = 2*t;
#pragma unroll
                for (int nj = 0; nj < 16; nj++) {
                    int c0 = c0b + nj*8, c1 = c0 + 1;
                    if (c0 > r0) s[nj][0] = -1e30f;
                    if (c1 > r0) s[nj][1] = -1e30f;
                    if (c0 > r1) s[nj][2] = -1e30f;
                    if (c1 > r1) s[nj][3] = -1e30f;
                }
            }

            // ---- online softmax ----
            float mx0 = -1e30f, mx1 = -1e30f;
#pragma unroll
            for (int nj = 0; nj < 16; nj++) {
                mx0 = fmaxf(mx0, fmaxf(s[nj][0], s[nj][1]));
                mx1 = fmaxf(mx1, fmaxf(s[nj][2], s[nj][3]));
            }
            mx0 = fmaxf(mx0, __shfl_xor_sync(0xffffffffu, mx0, 1));
            mx0 = fmaxf(mx0, __shfl_xor_sync(0xffffffffu, mx0, 2));
            mx1 = fmaxf(mx1, __shfl_xor_sync(0xffffffffu, mx1, 1));
            mx1 = fmaxf(mx1, __shfl_xor_sync(0xffffffffu, mx1, 2));
            float mn0 = fmaxf(m0, mx0), mn1 = fmaxf(m1, mx1);
            float al0 = __expf(m0 - mn0), al1 = __expf(m1 - mn1);
            m0 = mn0; m1 = mn1;

            float rs0 = 0.f, rs1 = 0.f;
#pragma unroll
            for (int nj = 0; nj < 16; nj++) {
                s[nj][0] = __expf(s[nj][0] - mn0);
                s[nj][1] = __expf(s[nj][1] - mn0);
                s[nj][2] = __expf(s[nj][2] - mn1);
                s[nj][3] = __expf(s[nj][3] - mn1);
                rs0 += s[nj][0] + s[nj][1];
                rs1 += s[nj][2] + s[nj][3];
            }
            rs0 += __shfl_xor_sync(0xffffffffu, rs0, 1);
            rs0 += __shfl_xor_sync(0xffffffffu, rs0, 2);
            rs1 += __shfl_xor_sync(0xffffffffu, rs1, 1);
            rs1 += __shfl_xor_sync(0xffffffffu, rs1, 2);
            l0 = l0 * al0 + rs0;
            l1 = l1 * al1 + rs1;

#pragma unroll
            for (int nj = 0; nj < 16; nj++) {
                o[nj][0] *= al0; o[nj][1] *= al0;
                o[nj][2] *= al1; o[nj][3] *= al1;
            }

            // ---- O += P @ V : P packs directly into A-frags (kt 0..7) ----
#pragma unroll
            for (int kt = 0; kt < 8; kt++) {
                uint4 a;
                a.x = pack_h2(s[2*kt  ][0], s[2*kt  ][1]);
                a.y = pack_h2(s[2*kt  ][2], s[2*kt  ][3]);
                a.z = pack_h2(s[2*kt+1][0], s[2*kt+1][1]);
                a.w = pack_h2(s[2*kt+1][2], s[2*kt+1][3]);
#pragma unroll
                for (int q = 0; q < 8; q++) {
                    uint4 bp;
                    ldsm_x4_t(bp, sV + (unsigned)((16*kt + vb_row)*FA_ST
                                                  + q*16 + vb_colh)*2u);
                    mma_f16(o[2*q  ], a, bp.x, bp.y);
                    mma_f16(o[2*q+1], a, bp.z, bp.w);
                }
            }
            __syncthreads();
        }

        // ---- epilogue ----
        float il0 = 1.0f / l0, il1 = 1.0f / l1;
#pragma unroll
        for (int nj = 0; nj < 16; nj++) {
            int row0 = qb*FAQ + w16 + g;
            int col  = h*HD + nj*8 + 2*t;
            __half2 v0 = __floats2half2_rn(o[nj][0]*il0, o[nj][1]*il0);
            __half2 v1 = __floats2half2_rn(o[nj][2]*il1, o[nj][3]*il1);
            *(__half2*)&att[(size_t)row0 * NQ + col]       = v0;
            *(__half2*)&att[(size_t)(row0 + 8) * NQ + col] = v1;
        }
        __syncthreads();
    }
}

// ---------------------------------------------------------------------------
extern "C" void kernel_launch(void* const* d_in, const int* in_sizes, int n_in,
                              void* d_out, int out_size)
{
    const float* x  = (const float*)d_in[0];
    const float* wq = (const float*)d_in[1];
    const float* wk = (const float*)d_in[2];
    const float* wv = (const float*)d_in[3];
    const float* wo = (const float*)d_in[4];
    const float* cs = (const float*)d_in[5];
    const float* sn = (const float*)d_in[6];
    float* out = (float*)d_out;

    __half *qkvh, *atth, *xh, *wqkvh, *worh; void* ctrs;
    cudaGetSymbolAddress((void**)&qkvh,  g_qkvh);
    cudaGetSymbolAddress((void**)&atth,  g_atth);
    cudaGetSymbolAddress((void**)&xh,    g_xh);
    cudaGetSymbolAddress((void**)&wqkvh, g_wqkvh);
    cudaGetSymbolAddress((void**)&worh,  g_worh);
    cudaGetSymbolAddress(&ctrs,          g_ctrs);

    static int nsm = 0;
    if (nsm == 0) {
        cudaDeviceGetAttribute(&nsm, cudaDevAttrMultiProcessorCount, 0);
        if (nsm <= 0) nsm = 148;
        cudaFuncSetAttribute(qkv_gemm_kernel,
            cudaFuncAttributeMaxDynamicSharedMemorySize, GEMM_SMEM);
        cudaFuncSetAttribute(oproj_gemm_kernel,
            cudaFuncAttributeMaxDynamicSharedMemorySize, GEMM_SMEM);
        cudaFuncSetAttribute(fa_f16_kernel,
            cudaFuncAttributeMaxDynamicSharedMemorySize, FA_SMEM);
    }

    cudaMemsetAsync(ctrs, 0, 2*sizeof(unsigned));

    // Round inputs once to fp16 (10-bit mantissa — same as tf32)
    round_all_kernel<<<(R_TOT + 255)/256, 256>>>(
        x, wq, wk, wv, wo, xh, wqkvh, worh);

    // QKV projection with fused RoPE + fp16 epilogue
    const float scale = 0.08838834764831845f;  // 128^-0.5
    qkv_gemm_kernel<<<dim3(QKVW/128, TT/128), 256, GEMM_SMEM>>>(
        xh, wqkvh, qkvh, cs, sn, scale);

    // fp16 flash attention (BKV=128), persistent work-steal
    fa_f16_kernel<<<dim3(nsm, 1), 256, FA_SMEM>>>(atth);

    // Output projection (fp32 out)
    oproj_gemm_kernel<<<dim3(DIMD/128, TT/128), 256, GEMM_SMEM>>>(atth, worh, out);
}